// round 5
// baseline (speedup 1.0000x reference)
#include <cuda_runtime.h>
#include <math_constants.h>

#define NS     5000
#define SPTS   10
#define NSEG   9
#define KNN    20
#define HH     512
#define WW     512
#define HC     102
#define WC     102
#define NCELL  (HC*WC)

// ---------------- scratch (static device globals; no runtime allocation) ----
__device__ float4 g_seg[NS * NSEG];         // per segment: ax, ay, bx, by
__device__ float  g_d2[NS * NSEG];          // per segment: bx^2+by^2 (ref rounding)
__device__ float4 g_bbox[NS];               // per stroke: cx, cy, hx+eps, hy+eps
__device__ float4 g_colw[NS];               // rgb + width packed
__device__ int    g_tidx[NCELL * KNN];      // per coarse cell: sorted top-K stroke ids
__device__ float  g_tw[NCELL * KNN];        // per coarse cell: width of slot-k stroke

// ---------------- kernel 1: bezier -> segments, bbox, color/width -----------
// Amplified path ops individually rounded (no FMA), matching XLA.
__global__ void k_bezier(const float* __restrict__ cs, const float* __restrict__ ce,
                         const float* __restrict__ cc, const float* __restrict__ color,
                         const float* __restrict__ loc, const float* __restrict__ width)
{
    int n = blockIdx.x * blockDim.x + threadIdx.x;
    if (n >= NS) return;
    float lx = loc[2*n], ly = loc[2*n+1];
    float Sx = __fadd_rn(cs[2*n],   lx), Sy = __fadd_rn(cs[2*n+1], ly);
    float Ex = __fadd_rn(ce[2*n],   lx), Ey = __fadd_rn(ce[2*n+1], ly);
    float Cx = __fadd_rn(cc[2*n],   lx), Cy = __fadd_rn(cc[2*n+1], ly);
    float dsx = __fsub_rn(Sx, Cx), dsy = __fsub_rn(Sy, Cy);
    float dex = __fsub_rn(Ex, Cx), dey = __fsub_rn(Ey, Cy);
    float step = __fdiv_rn(1.0f, 9.0f);
    float ptx[SPTS], pty[SPTS];
    float mnx = CUDART_INF_F, mxx = -CUDART_INF_F;
    float mny = CUDART_INF_F, mxy = -CUDART_INF_F;
    #pragma unroll
    for (int i = 0; i < SPTS; i++) {
        float t   = __fmul_rn((float)i, step);
        float omt = __fsub_rn(1.0f, t);
        float o2  = __fmul_rn(omt, omt);
        float t2  = __fmul_rn(t, t);
        float px = __fadd_rn(__fadd_rn(Cx, __fmul_rn(o2, dsx)), __fmul_rn(t2, dex));
        float py = __fadd_rn(__fadd_rn(Cy, __fmul_rn(o2, dsy)), __fmul_rn(t2, dey));
        ptx[i] = px; pty[i] = py;
        mnx = fminf(mnx, px); mxx = fmaxf(mxx, px);
        mny = fminf(mny, py); mxy = fmaxf(mxy, py);
    }
    #pragma unroll
    for (int s = 0; s < NSEG; s++) {
        float bx = __fsub_rn(ptx[s+1], ptx[s]);
        float by = __fsub_rn(pty[s+1], pty[s]);
        g_seg[n*NSEG + s] = make_float4(ptx[s], pty[s], bx, by);
        g_d2 [n*NSEG + s] = __fadd_rn(__fmul_rn(bx, bx), __fmul_rn(by, by));
    }
    g_bbox[n] = make_float4(0.5f*(mnx+mxx), 0.5f*(mny+mxy),
                            0.5f*(mxx-mnx) + 1e-3f, 0.5f*(mxy-mny) + 1e-3f);
    g_colw[n] = make_float4(color[3*n], color[3*n+1], color[3*n+2], width[n]);
}

// ---------------- kernel 2: coarse-grid top-K nearest strokes ---------------
// 2 threads/cell on index-parity subsets; register-resident branchless
// compare-swap insertion; lexicographic 2-way merge reproduces jax.lax.top_k
// stable tie order. Distances use exact reference rounding.
#define PARTS  2
#define CPB    64                 // cells per block (128 threads)
#define TILE2  1024
__global__ void __launch_bounds__(CPB*PARTS) k_topk(const float* __restrict__ loc,
                                                    const float* __restrict__ width)
{
    __shared__ float2 sl[TILE2];
    __shared__ float2 sml[CPB][PARTS][KNN];   // (d, idx-bits)

    int c    = threadIdx.x >> 1;              // local cell 0..63
    int part = threadIdx.x & 1;
    int cell = blockIdx.x * CPB + c;
    bool active = (cell < NCELL);
    float px = 0.f, py = 0.f;
    if (active) {
        int ci = cell / WC, cj = cell % WC;
        float step = __fdiv_rn(512.0f, 101.0f);   // linspace(0,512,102)
        px = __fmul_rn((float)ci, step);
        py = __fmul_rn((float)cj, step);
    }
    float bd[KNN]; int bi[KNN];
    #pragma unroll
    for (int k = 0; k < KNN; k++) { bd[k] = CUDART_INF_F; bi[k] = 0x7fffffff; }

    for (int base = 0; base < NS; base += TILE2) {
        int cnt = min(TILE2, NS - base);
        __syncthreads();
        for (int i = threadIdx.x; i < cnt; i += blockDim.x)
            sl[i] = ((const float2*)loc)[base + i];
        __syncthreads();
        if (active) {
            for (int i = part; i < cnt; i += PARTS) {
                float dx = __fsub_rn(px, sl[i].x);
                float dy = __fsub_rn(py, sl[i].y);
                float d  = __fadd_rn(__fmul_rn(dx, dx), __fmul_rn(dy, dy));
                if (d < bd[KNN-1]) {
                    float id = d; int ii = base + i;
                    #pragma unroll
                    for (int j = 0; j < KNN; j++) {
                        bool sw = id < bd[j];
                        float td = bd[j]; int ti = bi[j];
                        if (sw) { bd[j] = id; bi[j] = ii; id = td; ii = ti; }
                    }
                }
            }
        }
    }
    __syncthreads();
    #pragma unroll
    for (int k = 0; k < KNN; k++)
        sml[c][part][k] = make_float2(bd[k], __int_as_float(bi[k]));
    __syncthreads();

    if (active && part == 0) {
        int p0 = 0, p1 = 0;
        #pragma unroll
        for (int k = 0; k < KNN; k++) {
            float2 v0 = sml[c][0][p0];
            float2 v1 = sml[c][1][p1];
            float d0 = v0.x; int i0 = __float_as_int(v0.y);
            float d1 = v1.x; int i1 = __float_as_int(v1.y);
            bool take0 = (d0 < d1) || (d0 == d1 && i0 < i1);
            int besti = take0 ? i0 : i1;
            if (take0) p0++; else p1++;
            g_tidx[cell*KNN + k] = besti;
            g_tw  [cell*KNN + k] = __ldg(width + besti);
        }
    }
}

// ---------------- render helpers --------------------------------------------
// Exact (XLA per-op-rounded) min segment distance^2 for one stroke.
__device__ __forceinline__ float stroke_dist2(int idx, float pxf, float pyf)
{
    const float4* sp = g_seg + idx * NSEG;
    const float*  dp = g_d2  + idx * NSEG;
    float m = CUDART_INF_F;
    #pragma unroll
    for (int s = 0; s < NSEG; s++) {
        float4 sg = __ldg(sp + s);
        float d2  = __ldg(dp + s);
        float pax = __fsub_rn(pxf, sg.x);
        float pay = __fsub_rn(pyf, sg.y);
        float dot1 = __fadd_rn(__fmul_rn(sg.z, pax), __fmul_rn(sg.w, pay));
        float t = __fdiv_rn(dot1, d2);
        t = fminf(fmaxf(t, 0.0f), 1.0f);
        float cx = __fadd_rn(sg.x, __fmul_rn(t, sg.z));
        float cy = __fadd_rn(sg.y, __fmul_rn(t, sg.w));
        float dx = __fsub_rn(pxf, cx);
        float dy = __fsub_rn(pyf, cy);
        float d = __fadd_rn(__fmul_rn(dx, dx), __fmul_rn(dy, dy));
        m = fminf(m, d);
    }
    return m;
}

// ---------------- kernel 3: full-res shading with fixed-threshold culling ---
// k=0 (nearest stroke by construction) is peeled; strokes k>=1 whose
// conservative bbox lower-bound distance proves r_k < r0 - 127.9 contribute
// exactly 0 to the softmax (fp32 exp underflow) and cannot affect D, so
// skipping them is bit-identical. The threshold is FIXED after k=0, keeping
// iterations 1..19 mutually independent (full ILP — the R3 mistake avoided).
__global__ void __launch_bounds__(256, 2) k_render(float* __restrict__ out)
{
    int lane = threadIdx.x & 31;
    int wrp  = threadIdx.x >> 5;       // 0..7
    int subx = lane & 7, suby = lane >> 3;
    int wx = wrp & 1,  wy = wrp >> 1;
    int w = blockIdx.x * 16 + wx * 8 + subx;   // width index (second coord)
    int h = blockIdx.y * 16 + wy * 4 + suby;   // height index (first coord)

    float stepf = __fdiv_rn(512.0f, 511.0f);   // linspace(0,512,512)
    float pxf = __fmul_rn((float)h, stepf);
    float pyf = __fmul_rn((float)w, stepf);

    // nearest-upsample coarse cell (exact: 102/512 = 51/256 exact in f32)
    int ch = min((int)((float)h * 0.19921875f), HC - 1);
    int cw = min((int)((float)w * 0.19921875f), WC - 1);
    const int* idxp = g_tidx + (ch*WC + cw) * KNN;

    // half-pixel bilinear for the width resize (edge-clamped lerp ==
    // jax's renormalized triangle kernel at the borders); smooth path.
    float yc = ((float)h + 0.5f) * 0.19921875f - 0.5f;
    float xc = ((float)w + 0.5f) * 0.19921875f - 0.5f;
    float y0f = floorf(yc), x0f = floorf(xc);
    float fy = yc - y0f,    fx = xc - x0f;
    int y0 = max(0, min(HC-1, (int)y0f));
    int y1 = max(0, min(HC-1, (int)y0f + 1));
    int x0 = max(0, min(WC-1, (int)x0f));
    int x1 = max(0, min(WC-1, (int)x0f + 1));
    const float* pw00 = g_tw + (y0*WC + x0) * KNN;
    const float* pw01 = g_tw + (y0*WC + x1) * KNN;
    const float* pw10 = g_tw + (y1*WC + x0) * KNN;
    const float* pw11 = g_tw + (y1*WC + x1) * KNN;
    float c00 = (1.f-fy)*(1.f-fx), c01 = (1.f-fy)*fx;
    float c10 = fy*(1.f-fx),       c11 = fy*fx;

    // ---- peel k = 0 (nearest stroke: establishes the fixed cull threshold)
    int idx0 = __ldg(idxp);
    float m0 = stroke_dist2(idx0, pxf, pyf);
    float D  = m0;
    float r0 = __fmul_rn(100000.0f, __fdiv_rn(1.0f, __fadd_rn(1e-8f, m0)));
    float M  = r0;
    float4 col0 = __ldg(&g_colw[idx0]);
    float wk0 = c00*__ldg(pw00) + c01*__ldg(pw01)
              + c10*__ldg(pw10) + c11*__ldg(pw11);
    float sum = 1.0f;
    float a0 = col0.x, a1 = col0.y, a2 = col0.z, bw = wk0;

    // cull threshold on bbox lower-bound distance^2 (conservative slacks;
    // multiplicative so it stays valid at large r0). r0<=128 -> disabled.
    float thr = r0 - 128.0f;
    float cullT = (thr > 0.0f) ? __fdividef(100000.0f, thr) * 1.0001f
                               : CUDART_INF_F;

    #pragma unroll 2
    for (int k = 1; k < KNN; k++) {
        int idx = __ldg(idxp + k);
        float4 bb = __ldg(&g_bbox[idx]);
        float ddx = fmaxf(fabsf(pxf - bb.x) - bb.z, 0.0f);
        float ddy = fmaxf(fabsf(pyf - bb.y) - bb.w, 0.0f);
        float lb  = (ddx*ddx + ddy*ddy) * 0.999f;   // shrunk lower bound

        if (lb <= cullT) {
            float m = stroke_dist2(idx, pxf, pyf);
            D = fminf(D, m);
            float r = __fmul_rn(100000.0f, __fdiv_rn(1.0f, __fadd_rn(1e-8f, m)));

            float wk = c00*__ldg(pw00+k) + c01*__ldg(pw01+k)
                     + c10*__ldg(pw10+k) + c11*__ldg(pw11+k);
            float4 col = __ldg(&g_colw[idx]);

            float newM = fmaxf(r, M);
            float sc = __expf(M - newM);
            float e  = __expf(r - newM);
            sum = sum*sc + e;
            a0  = a0 *sc + e*col.x;
            a1  = a1 *sc + e*col.y;
            a2  = a2 *sc + e*col.z;
            bw  = bw *sc + e*wk;
            M = newM;
        }
    }

    float inv  = __fdividef(1.0f, sum);
    float bs   = bw * inv;
    float mask = __fdividef(1.0f, 1.0f + __expf(-(bs - D)));
    float om   = 1.0f - mask;
    int o = (h * WW + w) * 3;
    out[o+0] = a0*inv*mask + om*0.5f;
    out[o+1] = a1*inv*mask + om*0.5f;
    out[o+2] = a2*inv*mask + om*0.5f;
}

// ---------------- launch ----------------------------------------------------
extern "C" void kernel_launch(void* const* d_in, const int* in_sizes, int n_in,
                              void* d_out, int out_size)
{
    const float* curve_s  = (const float*)d_in[0];
    const float* curve_e  = (const float*)d_in[1];
    const float* curve_c  = (const float*)d_in[2];
    const float* color    = (const float*)d_in[3];
    const float* location = (const float*)d_in[4];
    const float* width    = (const float*)d_in[5];
    float* out = (float*)d_out;

    k_bezier<<<(NS + 255) / 256, 256>>>(curve_s, curve_e, curve_c, color, location, width);
    k_topk<<<(NCELL + CPB - 1) / CPB, CPB * PARTS>>>(location, width);
    dim3 grid(WW / 16, HH / 16);
    k_render<<<grid, 256>>>(out);
}